// round 2
// baseline (speedup 1.0000x reference)
#include <cuda_runtime.h>
#include <cstdint>

#define KCODES 512
#define NPAIRS 256           // code pairs
#define DDIM 64
#define HW 4096
#define MPTS 262144          // N*H*W points
#define ZQ_ELEMS 16777216    // N*D*H*W
#define THREADS 256          // 1 point per thread
#define NBLK (MPTS / THREADS)
#define SPAIR 132            // floats per pair-row (128 + pad)

__device__ double g_loss_sum;

__global__ void vq_zero_loss() { g_loss_sum = 0.0; }
__global__ void vq_finalize(float* out) {
    out[ZQ_ELEMS] = (float)(g_loss_sum / (double)ZQ_ELEMS);
}

__device__ __forceinline__ uint64_t pack2(float a, float b) {
    uint64_t r; asm("mov.b64 %0, {%1, %2};" : "=l"(r) : "f"(a), "f"(b)); return r;
}
__device__ __forceinline__ void unpack2(uint64_t v, float& a, float& b) {
    asm("mov.b64 {%0, %1}, %2;" : "=f"(a), "=f"(b) : "l"(v));
}
__device__ __forceinline__ void fma2(uint64_t& acc, uint64_t a, uint64_t b) {
    asm("fma.rn.f32x2 %0, %1, %2, %0;" : "+l"(acc) : "l"(a), "l"(b));
}
__device__ __forceinline__ uint64_t add2(uint64_t a, uint64_t b) {
    uint64_t r; asm("add.rn.f32x2 %0, %1, %2;" : "=l"(r) : "l"(a), "l"(b)); return r;
}
__device__ __forceinline__ uint64_t mul2(uint64_t a, uint64_t b) {
    uint64_t r; asm("mul.rn.f32x2 %0, %1, %2;" : "=l"(r) : "l"(a), "l"(b)); return r;
}

__global__ __launch_bounds__(THREADS, 1)
void vq_main(const float* __restrict__ z, const float* __restrict__ emb,
             float* __restrict__ out) {
    extern __shared__ float smem[];
    float* sm_e = smem;                                  // NPAIRS * SPAIR, pair-interleaved
    uint64_t* sm_q = (uint64_t*)(smem + NPAIRS * SPAIR); // packed (e_sq_{2k}, e_sq_{2k+1})

    const int tid = threadIdx.x;

    // Pair-interleaved embedding: sm_e[pair][2d + (k&1)] = emb[k][d]
    for (int idx = tid; idx < KCODES * DDIM; idx += THREADS) {
        int k = idx >> 6, d = idx & 63;
        sm_e[(k >> 1) * SPAIR + (d << 1) + (k & 1)] = emb[idx];
    }
    __syncthreads();

    // e_sq per code: sequential fp32 (mul rounded, then add rounded), d = 0..63
    {
        const float* row = sm_e + tid * SPAIR;
        float q0 = 0.f, q1 = 0.f;
        #pragma unroll
        for (int d = 0; d < DDIM; d++) {
            q0 = __fadd_rn(q0, __fmul_rn(row[2 * d],     row[2 * d]));
            q1 = __fadd_rn(q1, __fmul_rn(row[2 * d + 1], row[2 * d + 1]));
        }
        sm_q[tid] = pack2(q0, q1);
    }
    __syncthreads();

    const int p  = blockIdx.x * THREADS + tid;
    const int n  = p >> 12;
    const int hw = p & (HW - 1);
    const float* zp = z + (size_t)n * (DDIM * HW) + hw;

    // Load z, compute z_sq sequentially (mul then add, ascending d), dup-pack z
    uint64_t zz[DDIM];
    float S = 0.f;
    #pragma unroll
    for (int d = 0; d < DDIM; d++) {
        float v = zp[d * HW];
        S = __fadd_rn(S, __fmul_rn(v, v));
        zz[d] = pack2(v, v);
    }
    const uint64_t SS = pack2(S, S);
    const uint64_t M2 = pack2(-2.0f, -2.0f);

    float best = __int_as_float(0x7f800000);  // +inf
    int bi = 0;

    #pragma unroll 1
    for (int g = 0; g < NPAIRS / 4; g++) {
        const ulonglong2* r0 = (const ulonglong2*)(sm_e + (4 * g + 0) * SPAIR);
        const ulonglong2* r1 = (const ulonglong2*)(sm_e + (4 * g + 1) * SPAIR);
        const ulonglong2* r2 = (const ulonglong2*)(sm_e + (4 * g + 2) * SPAIR);
        const ulonglong2* r3 = (const ulonglong2*)(sm_e + (4 * g + 3) * SPAIR);
        uint64_t a0 = 0ull, a1 = 0ull, a2 = 0ull, a3 = 0ull;
        // Sequential FMA chain over d (each f32x2 lane = one code's scalar fmaf chain)
        #pragma unroll
        for (int d2 = 0; d2 < DDIM / 2; d2++) {
            ulonglong2 e0 = r0[d2], e1 = r1[d2], e2 = r2[d2], e3 = r3[d2];
            fma2(a0, zz[2 * d2],     e0.x);
            fma2(a1, zz[2 * d2],     e1.x);
            fma2(a2, zz[2 * d2],     e2.x);
            fma2(a3, zz[2 * d2],     e3.x);
            fma2(a0, zz[2 * d2 + 1], e0.y);
            fma2(a1, zz[2 * d2 + 1], e1.y);
            fma2(a2, zz[2 * d2 + 1], e2.y);
            fma2(a3, zz[2 * d2 + 1], e3.y);
        }
        // dist = fl( fl(z_sq + e_sq) - 2*dot ); argmin, first index on ties
        #pragma unroll
        for (int j = 0; j < 4; j++) {
            uint64_t acc = (j == 0) ? a0 : (j == 1) ? a1 : (j == 2) ? a2 : a3;
            int pr = 4 * g + j;
            uint64_t A  = add2(SS, sm_q[pr]);       // fl(z_sq + e_sq), packed
            uint64_t dd = add2(A, mul2(acc, M2));   // fl(A - 2*dot),   packed
            float dlo, dhi; unpack2(dd, dlo, dhi);
            if (dlo < best) { best = dlo; bi = 2 * pr; }
            if (dhi < best) { best = dhi; bi = 2 * pr + 1; }
        }
    }

    // Epilogue: straight-through z_q, loss, index
    const float* brow = sm_e + (bi >> 1) * SPAIR;
    const int lane = bi & 1;
    float* outz = out + (size_t)n * (DDIM * HW) + hw;
    double lsum = 0.0;
    #pragma unroll
    for (int d = 0; d < DDIM; d++) {
        float e = brow[(d << 1) + lane];
        float zv, dummy; unpack2(zz[d], zv, dummy);
        float diff = __fsub_rn(e, zv);              // fl(z_q - z)
        outz[d * HW] = __fadd_rn(zv, diff);         // fl(z + fl(z_q - z))
        float ld = __fsub_rn(zv, e);                // fl(z - z_q)
        lsum += (double)ld * (double)ld;
    }
    out[ZQ_ELEMS + 1 + p] = (float)bi;

    // warp-reduce loss, one double atomic per warp
    #pragma unroll
    for (int off = 16; off > 0; off >>= 1)
        lsum += __shfl_down_sync(0xffffffffu, lsum, off);
    if ((tid & 31) == 0) atomicAdd(&g_loss_sum, lsum);
}

extern "C" void kernel_launch(void* const* d_in, const int* in_sizes, int n_in,
                              void* d_out, int out_size) {
    const float* z   = (const float*)d_in[0];   // z_e (64,64,64,64) f32
    const float* emb = (const float*)d_in[1];   // emb_weight (512,64) f32
    float* out = (float*)d_out;

    size_t smem_bytes = (size_t)NPAIRS * SPAIR * sizeof(float)
                      + (size_t)NPAIRS * sizeof(uint64_t);
    cudaFuncSetAttribute(vq_main, cudaFuncAttributeMaxDynamicSharedMemorySize,
                         (int)smem_bytes);

    vq_zero_loss<<<1, 1>>>();
    vq_main<<<NBLK, THREADS, smem_bytes>>>(z, emb, out);
    vq_finalize<<<1, 1>>>(out);
}

// round 3
// speedup vs baseline: 1.1930x; 1.1930x over previous
#include <cuda_runtime.h>
#include <cstdint>

#define KCODES 512
#define NPAIRS 256           // code pairs
#define DDIM 64
#define HW 4096
#define MPTS 262144          // N*H*W points
#define ZQ_ELEMS 16777216    // N*D*H*W
#define THREADS 256
#define PTSB 512             // points per block (2 per thread)
#define NBLK (MPTS / PTSB)   // 512 blocks
#define SPAIR 128            // floats per pair-row (512B, 16B-aligned)

__device__ double g_loss_sum;
__device__ unsigned g_ctr;

__global__ void vq_prep() { g_loss_sum = 0.0; g_ctr = 0u; }

__device__ __forceinline__ uint64_t pack2(float a, float b) {
    uint64_t r; asm("mov.b64 %0, {%1, %2};" : "=l"(r) : "f"(a), "f"(b)); return r;
}
// volatile: exactly one MOV per source occurrence (no hoist/CSE into 128 live regs)
__device__ __forceinline__ uint64_t dup2(float a) {
    uint64_t r; asm volatile("mov.b64 %0, {%1, %1};" : "=l"(r) : "f"(a)); return r;
}
__device__ __forceinline__ void unpack2(uint64_t v, float& a, float& b) {
    asm("mov.b64 {%0, %1}, %2;" : "=f"(a), "=f"(b) : "l"(v));
}
__device__ __forceinline__ void fma2(uint64_t& acc, uint64_t a, uint64_t b) {
    asm("fma.rn.f32x2 %0, %1, %2, %0;" : "+l"(acc) : "l"(a), "l"(b));
}
__device__ __forceinline__ uint64_t add2(uint64_t a, uint64_t b) {
    uint64_t r; asm("add.rn.f32x2 %0, %1, %2;" : "=l"(r) : "l"(a), "l"(b)); return r;
}
__device__ __forceinline__ uint64_t mul2(uint64_t a, uint64_t b) {
    uint64_t r; asm("mul.rn.f32x2 %0, %1, %2;" : "=l"(r) : "l"(a), "l"(b)); return r;
}

__global__ __launch_bounds__(THREADS, 1)
void vq_main(const float* __restrict__ z, const float* __restrict__ emb,
             float* __restrict__ out) {
    extern __shared__ float smem[];
    float* sm_e = smem;                                  // NPAIRS * SPAIR, pair-interleaved
    uint64_t* sm_q = (uint64_t*)(smem + NPAIRS * SPAIR); // packed (e_sq_{2k}, e_sq_{2k+1})

    const int tid = threadIdx.x;

    // Pair-interleaved embedding: sm_e[pair][2d + (k&1)] = emb[k][d]
    for (int idx = tid; idx < KCODES * DDIM; idx += THREADS) {
        int k = idx >> 6, d = idx & 63;
        sm_e[(k >> 1) * SPAIR + (d << 1) + (k & 1)] = emb[idx];
    }
    __syncthreads();

    // e_sq per code: sequential fp32 (mul rounded, then add rounded), d = 0..63
    {
        const float* row = sm_e + tid * SPAIR;
        float q0 = 0.f, q1 = 0.f;
        #pragma unroll
        for (int d = 0; d < DDIM; d++) {
            q0 = __fadd_rn(q0, __fmul_rn(row[2 * d],     row[2 * d]));
            q1 = __fadd_rn(q1, __fmul_rn(row[2 * d + 1], row[2 * d + 1]));
        }
        sm_q[tid] = pack2(q0, q1);
    }
    __syncthreads();

    // Two points per thread: p0 = base+tid, p1 = base+256+tid (same n: 512 | 4096)
    const int p0 = blockIdx.x * PTSB + tid;
    const int p1 = p0 + 256;
    const int n  = p0 >> 12;
    const int h0 = p0 & (HW - 1);
    const int h1 = p1 & (HW - 1);
    const float* zbase = z + (size_t)n * (DDIM * HW);

    // Load z, compute z_sq sequentially (mul then add, ascending d)
    float zf0[DDIM], zf1[DDIM];
    float S0 = 0.f, S1 = 0.f;
    #pragma unroll
    for (int d = 0; d < DDIM; d++) {
        float v0 = zbase[d * HW + h0];
        float v1 = zbase[d * HW + h1];
        S0 = __fadd_rn(S0, __fmul_rn(v0, v0));
        S1 = __fadd_rn(S1, __fmul_rn(v1, v1));
        zf0[d] = v0; zf1[d] = v1;
    }
    const uint64_t SS0 = pack2(S0, S0);
    const uint64_t SS1 = pack2(S1, S1);
    const uint64_t M2  = pack2(-2.0f, -2.0f);

    const float INF = __int_as_float(0x7f800000);
    float best0 = INF, best1 = INF;
    int bi0 = 0, bi1 = 0;

    #pragma unroll 1
    for (int g = 0; g < NPAIRS / 4; g++) {
        const ulonglong2* r0 = (const ulonglong2*)(sm_e + (4 * g + 0) * SPAIR);
        const ulonglong2* r1 = (const ulonglong2*)(sm_e + (4 * g + 1) * SPAIR);
        const ulonglong2* r2 = (const ulonglong2*)(sm_e + (4 * g + 2) * SPAIR);
        const ulonglong2* r3 = (const ulonglong2*)(sm_e + (4 * g + 3) * SPAIR);
        uint64_t a00 = 0, a01 = 0, a02 = 0, a03 = 0;   // point 0, rows 0..3
        uint64_t a10 = 0, a11 = 0, a12 = 0, a13 = 0;   // point 1, rows 0..3

        ulonglong2 c0 = r0[0], c1 = r1[0], c2 = r2[0], c3 = r3[0];
        #pragma unroll
        for (int d2 = 0; d2 < DDIM / 2; d2++) {
            ulonglong2 n0, n1, n2, n3;
            if (d2 < DDIM / 2 - 1) {                    // prefetch next iter's rows
                n0 = r0[d2 + 1]; n1 = r1[d2 + 1]; n2 = r2[d2 + 1]; n3 = r3[d2 + 1];
            }
            uint64_t pa = dup2(zf0[2 * d2]);
            uint64_t qa = dup2(zf1[2 * d2]);
            fma2(a00, pa, c0.x); fma2(a01, pa, c1.x); fma2(a02, pa, c2.x); fma2(a03, pa, c3.x);
            fma2(a10, qa, c0.x); fma2(a11, qa, c1.x); fma2(a12, qa, c2.x); fma2(a13, qa, c3.x);
            uint64_t pb = dup2(zf0[2 * d2 + 1]);
            uint64_t qb = dup2(zf1[2 * d2 + 1]);
            fma2(a00, pb, c0.y); fma2(a01, pb, c1.y); fma2(a02, pb, c2.y); fma2(a03, pb, c3.y);
            fma2(a10, qb, c0.y); fma2(a11, qb, c1.y); fma2(a12, qb, c2.y); fma2(a13, qb, c3.y);
            if (d2 < DDIM / 2 - 1) { c0 = n0; c1 = n1; c2 = n2; c3 = n3; }
        }

        // dist = fl( fl(z_sq + e_sq) - 2*dot ); argmin, first index on ties
        #pragma unroll
        for (int j = 0; j < 4; j++) {
            const int pr = 4 * g + j;
            const uint64_t eq = sm_q[pr];
            uint64_t acc0 = (j == 0) ? a00 : (j == 1) ? a01 : (j == 2) ? a02 : a03;
            uint64_t acc1 = (j == 0) ? a10 : (j == 1) ? a11 : (j == 2) ? a12 : a13;
            uint64_t dd0 = add2(add2(SS0, eq), mul2(acc0, M2));
            uint64_t dd1 = add2(add2(SS1, eq), mul2(acc1, M2));
            float lo, hi;
            unpack2(dd0, lo, hi);
            if (lo < best0) { best0 = lo; bi0 = 2 * pr; }
            if (hi < best0) { best0 = hi; bi0 = 2 * pr + 1; }
            unpack2(dd1, lo, hi);
            if (lo < best1) { best1 = lo; bi1 = 2 * pr; }
            if (hi < best1) { best1 = hi; bi1 = 2 * pr + 1; }
        }
    }

    // Epilogue: straight-through z_q, loss, indices (thread owns both points)
    float* outz = out + (size_t)n * (DDIM * HW);
    const float* brow0 = sm_e + (bi0 >> 1) * SPAIR;
    const float* brow1 = sm_e + (bi1 >> 1) * SPAIR;
    const int l0 = bi0 & 1, l1 = bi1 & 1;
    double lsum = 0.0;
    #pragma unroll
    for (int d = 0; d < DDIM; d++) {
        float e0 = brow0[(d << 1) + l0];
        float e1 = brow1[(d << 1) + l1];
        float v0 = zf0[d], v1 = zf1[d];
        outz[d * HW + h0] = __fadd_rn(v0, __fsub_rn(e0, v0)); // fl(z + fl(z_q - z))
        outz[d * HW + h1] = __fadd_rn(v1, __fsub_rn(e1, v1));
        float x0 = __fsub_rn(v0, e0);                         // fl(z - z_q)
        float x1 = __fsub_rn(v1, e1);
        lsum += (double)x0 * (double)x0;
        lsum += (double)x1 * (double)x1;
    }
    out[ZQ_ELEMS + 1 + p0] = (float)bi0;
    out[ZQ_ELEMS + 1 + p1] = (float)bi1;

    // warp-reduce loss, one double atomic per warp
    #pragma unroll
    for (int off = 16; off > 0; off >>= 1)
        lsum += __shfl_down_sync(0xffffffffu, lsum, off);
    if ((tid & 31) == 0) atomicAdd(&g_loss_sum, lsum);

    // last CTA finalizes the mean
    __syncthreads();
    __threadfence();
    if (tid == 0) {
        unsigned t = atomicAdd(&g_ctr, 1u);
        if (t == (unsigned)(NBLK - 1)) {
            double s = atomicAdd(&g_loss_sum, 0.0);
            out[ZQ_ELEMS] = (float)(s / (double)ZQ_ELEMS);
        }
    }
}

extern "C" void kernel_launch(void* const* d_in, const int* in_sizes, int n_in,
                              void* d_out, int out_size) {
    const float* z   = (const float*)d_in[0];   // z_e (64,64,64,64) f32
    const float* emb = (const float*)d_in[1];   // emb_weight (512,64) f32
    float* out = (float*)d_out;

    size_t smem_bytes = (size_t)NPAIRS * SPAIR * sizeof(float)
                      + (size_t)NPAIRS * sizeof(uint64_t);
    cudaFuncSetAttribute(vq_main, cudaFuncAttributeMaxDynamicSharedMemorySize,
                         (int)smem_bytes);

    vq_prep<<<1, 1>>>();
    vq_main<<<NBLK, THREADS, smem_bytes>>>(z, emb, out);
}